// round 12
// baseline (speedup 1.0000x reference)
#include <cuda_runtime.h>
#include <cuda_fp16.h>
#include <cuda_pipeline.h>
#include <mma.h>
#include <cstdint>

using namespace nvcuda;

// Problem constants
#define BATCH   512
#define IN_DIM  256
#define OUT_DIM 256
#define NROWS   68          // G + K (rows 0..66 spline, 67 silu)
#define CG      16          // channels per block (8 pairs)
#define NITER   8           // channel pairs per block
#define KD2     144         // dense K per pair: 2*68 = 136, padded to 144 (9 chunks)
#define MT      128         // M tile (batch)
#define NTILE   128         // N tile (outputs)
#define ZSPLIT  (IN_DIM / CG)   // 16
#define NTHREADS 320        // 256 MMA consumers + 64 producers
#define NCONS    256

// fp16 W copy: [k, c, n] layout, as 16B chunks (8 halfs). 8.9 MB.
#define WH_CHUNKS (NROWS * IN_DIM * OUT_DIM / 8)   // 557056
__device__ uint4 g_wh[WH_CHUNKS];

// smem (halfs, padded for conflict-free LDSM), DOUBLE buffered
#define A_STRIDE 152                         // 304B rows
#define B_STRIDE 136                         // 272B rows (17 x 16B)
#define A_BYTES  (MT * A_STRIDE * 2)         // 38912
#define B_BYTES  (KD2 * B_STRIDE * 2)        // 39168
#define SMEM_TOTAL (2 * A_BYTES + 2 * B_BYTES)   // 156160 (stage reuses this)

// named barriers (ids 1..4), all with count = NTHREADS
#define BAR_ARRIVE(id) asm volatile("bar.arrive %0, %1;" :: "r"(id), "r"(NTHREADS) : "memory")
#define BAR_SYNC(id)   asm volatile("bar.sync %0, %1;"   :: "r"(id), "r"(NTHREADS) : "memory")
// ready[b] = 1+b, free[b] = 3+b

// ---------------- convert w to fp16 ----------------
__global__ void __launch_bounds__(256, 8)
convert_w_kernel(const float* __restrict__ w)
{
    int i = blockIdx.x * 256 + threadIdx.x;
    const float4* src = (const float4*)w + (size_t)i * 2;
    float4 a = src[0];
    float4 b = src[1];
    __half2 h0 = __floats2half2_rn(a.x, a.y);
    __half2 h1 = __floats2half2_rn(a.z, a.w);
    __half2 h2 = __floats2half2_rn(b.x, b.y);
    __half2 h3 = __floats2half2_rn(b.z, b.w);
    uint4 o;
    o.x = *(unsigned*)&h0; o.y = *(unsigned*)&h1;
    o.z = *(unsigned*)&h2; o.w = *(unsigned*)&h3;
    g_wh[i] = o;
}

// ---------------- zero output (float4) ----------------
__global__ void __launch_bounds__(256, 1)
zero_out_kernel(float4* __restrict__ out)
{
    out[blockIdx.x * 256 + threadIdx.x] = make_float4(0.f, 0.f, 0.f, 0.f);
}

// ---------------- basis + silu into A image ----------------
// t = [-1,-1,-1, linspace(-1,1,65), 1,1,1]; interior knots exact multiples of 2^-5.
__device__ __forceinline__ void gen_A(__half* arow, float xv, int* prevj)
{
    if (*prevj >= 0) {
        int pj = *prevj;
#pragma unroll
        for (int d = 0; d < 4; d++) arow[pj + d] = __ushort_as_half(0);
    }
    float f = (xv + 1.0f) * 32.0f;
    int j = (int)floorf(f);
    j = min(max(j, 0), 63);
    float tj  = -1.0f + (float)j * 0.03125f;
    float tj1 = -1.0f + (float)(j + 1) * 0.03125f;
    if (xv < tj) j--; else if (xv >= tj1) j++;
    j = min(max(j, 0), 63);

    float kn[6];
#pragma unroll
    for (int d = 0; d < 6; d++)
        kn[d] = -1.0f + (float)min(max(j + d - 2, 0), 64) * 0.03125f;

    float L1 = xv - kn[2], L2 = xv - kn[1], L3 = xv - kn[0];
    float R1 = kn[3] - xv, R2 = kn[4] - xv, R3 = kn[5] - xv;

    float temp, saved;
    temp = 1.0f / (R1 + L1);
    float n0 = R1 * temp;
    float n1 = L1 * temp;
    temp = n0 / (R1 + L2);
    float m0 = R1 * temp;  saved = L2 * temp;
    temp = n1 / (R2 + L1);
    float m1 = saved + R2 * temp;  float m2 = L1 * temp;
    temp = m0 / (R1 + L3);
    float q0 = R1 * temp;  saved = L3 * temp;
    temp = m1 / (R2 + L2);
    float q1 = saved + R2 * temp;  saved = L2 * temp;
    temp = m2 / (R3 + L1);
    float q2 = saved + R3 * temp;  float q3 = L1 * temp;

    float silu = xv / (1.0f + __expf(-xv));

    arow[j + 0] = __float2half_rn(q0);
    arow[j + 1] = __float2half_rn(q1);
    arow[j + 2] = __float2half_rn(q2);
    arow[j + 3] = __float2half_rn(q3);
    arow[67]    = __float2half_rn(silu);
    *prevj = j;
}

// ---------------- main kernel: warp-specialized producer/consumer -------------
__global__ void __launch_bounds__(NTHREADS, 1)
kan_wmma_kernel(const float* __restrict__ x, float* __restrict__ out)
{
    extern __shared__ __align__(256) char smem[];
    __half* A[2] = { (__half*)smem, (__half*)(smem + A_BYTES) };
    __half* B[2] = { (__half*)(smem + 2 * A_BYTES),
                     (__half*)(smem + 2 * A_BYTES + B_BYTES) };

    const int tid = threadIdx.x;
    const int wid = tid >> 5;
    const int b0  = blockIdx.x * MT;
    const int ny  = blockIdx.y;         // n-half: cols [128*ny, ...)
    const int c0  = blockIdx.z * CG;

    // zero all smem once (pads stay zero forever)
    {
        uint4 z = make_uint4(0, 0, 0, 0);
        uint4* p = (uint4*)smem;
        for (int j = tid; j < SMEM_TOTAL / 16; j += NTHREADS) p[j] = z;
    }
    __syncthreads();

    if (wid >= 8) {
        // ================= PRODUCER warps (2 warps, 64 threads) =================
        const int pt = tid - NCONS;       // 0..63
        int prevj[2][2][2];               // [buf][row][ch]
#pragma unroll
        for (int a = 0; a < 2; a++)
#pragma unroll
            for (int b = 0; b < 2; b++)
#pragma unroll
                for (int d = 0; d < 2; d++) prevj[a][b][d] = -1;

        for (int p = 0; p < NITER; p++) {
            const int buf = p & 1;
            if (p >= 2) BAR_SYNC(3 + buf);   // wait: consumers done MMA(p-2) on buf

            // B: 2176 cp.async chunks over 64 threads
            {
                const int cp = c0 + 2 * p;
                uint4* dst = (uint4*)B[buf];
                for (int j = pt; j < 2 * NROWS * 16; j += 64) {
                    int k2 = j >> 4;                 // image row 0..135
                    int q  = j & 15;
                    int ch = cp + (k2 >= NROWS);
                    int k  = (k2 >= NROWS) ? k2 - NROWS : k2;
                    __pipeline_memcpy_async(dst + k2 * 17 + q,
                        g_wh + ((size_t)(k * IN_DIM + ch) * 32) + ny * 16 + q, 16);
                }
                __pipeline_commit();
            }
            // A: rows pt and pt+64, channels c0+2p, c0+2p+1 (overlaps with B fill)
#pragma unroll
            for (int r = 0; r < 2; r++) {
                int m = pt + r * 64;
                float2 xp = *(const float2*)(x + (size_t)(b0 + m) * IN_DIM + c0 + 2 * p);
                __half* arow = A[buf] + m * A_STRIDE;
                gen_A(arow,      xp.x, &prevj[buf][r][0]);
                gen_A(arow + 68, xp.y, &prevj[buf][r][1]);
            }
            __pipeline_wait_prior(0);
            BAR_ARRIVE(1 + buf);             // publish buf
        }
    } else {
        // ================= CONSUMER warps (8 warps, WMMA) =================
        const int wm = wid & 3;              // rows wm*32
        const int wn = wid >> 2;             // cols wn*64

        wmma::fragment<wmma::accumulator, 16, 16, 16, float> acc[2][4];
#pragma unroll
        for (int i = 0; i < 2; i++)
#pragma unroll
            for (int j = 0; j < 4; j++) wmma::fill_fragment(acc[i][j], 0.0f);

        for (int it = 0; it < NITER; it++) {
            const int buf = it & 1;
            BAR_SYNC(1 + buf);               // wait: buf produced

            const __half* Ab = A[buf];
            const __half* Bb = B[buf];
#pragma unroll
            for (int kk = 0; kk < KD2 / 16; kk++) {
                wmma::fragment<wmma::matrix_a, 16, 16, 16, __half, wmma::row_major> af[2];
                wmma::fragment<wmma::matrix_b, 16, 16, 16, __half, wmma::row_major> bf[4];
#pragma unroll
                for (int i = 0; i < 2; i++)
                    wmma::load_matrix_sync(af[i],
                        Ab + (wm * 32 + i * 16) * A_STRIDE + kk * 16, A_STRIDE);
#pragma unroll
                for (int j = 0; j < 4; j++)
                    wmma::load_matrix_sync(bf[j],
                        Bb + (kk * 16) * B_STRIDE + wn * 64 + j * 16, B_STRIDE);
#pragma unroll
                for (int i = 0; i < 2; i++)
#pragma unroll
                    for (int j = 0; j < 4; j++)
                        wmma::mma_sync(acc[i][j], af[i], bf[j], acc[i][j]);
            }
            if (it + 2 < NITER) BAR_ARRIVE(3 + buf);   // release buf for reuse
        }

        // stage accumulators after the global sync below
        __syncthreads();                     // (1) all warps done with A/B smem

        float* stage = (float*)smem;
#pragma unroll
        for (int i = 0; i < 2; i++)
#pragma unroll
            for (int j = 0; j < 4; j++)
                wmma::store_matrix_sync(
                    stage + (wm * 32 + i * 16) * NTILE + wn * 64 + j * 16,
                    acc[i][j], NTILE, wmma::mem_row_major);
        goto epilogue_join;
    }
    __syncthreads();                         // (1) producers join
    goto epilogue_join2;

epilogue_join:
    __syncthreads();                         // (2) stage complete
    goto epilogue_write;
epilogue_join2:
    __syncthreads();                         // (2) producers join
epilogue_write:
    {
        const float* stage = (const float*)smem;
        float* dstb = out + (size_t)b0 * OUT_DIM + ny * NTILE;
        const float4* st4 = (const float4*)stage;
        for (int q = tid; q < (MT * NTILE) / 4; q += NTHREADS) {
            int mm = q >> 5;
            int nn = q & 31;
            float4 v = st4[q];
            float* d = dstb + (size_t)mm * OUT_DIM + nn * 4;
            atomicAdd(d + 0, v.x);
            atomicAdd(d + 1, v.y);
            atomicAdd(d + 2, v.z);
            atomicAdd(d + 3, v.w);
        }
    }
}

extern "C" void kernel_launch(void* const* d_in, const int* in_sizes, int n_in,
                              void* d_out, int out_size)
{
    const float* x = (const float*)d_in[0];
    const float* w = (const float*)d_in[1];
    float* out = (float*)d_out;

    cudaFuncSetAttribute(kan_wmma_kernel,
                         cudaFuncAttributeMaxDynamicSharedMemorySize, SMEM_TOTAL);

    convert_w_kernel<<<WH_CHUNKS / 256, 256>>>(w);
    zero_out_kernel<<<(BATCH * OUT_DIM / 4) / 256, 256>>>((float4*)out);

    dim3 grid(BATCH / MT, OUT_DIM / NTILE, ZSPLIT);
    kan_wmma_kernel<<<grid, NTHREADS, SMEM_TOTAL>>>(x, out);
}